// round 9
// baseline (speedup 1.0000x reference)
#include <cuda_runtime.h>
#include <cuda_bf16.h>
#include <math.h>

// Problem constants
#define Bn   8
#define Tn   1024
#define Cn   1024
#define Hn   16
#define HSn  64
#define NBn  63
#define WINn 128
#define EPSf 1e-5f

// ---------------- scratch (device globals; no allocation) ----------------
__device__ float g_qkv [Bn * Tn * 3 * Cn];        // [B,T,3C]
__device__ float g_kc  [Bn * Hn * NBn * HSn];     // [B,H,NB,hs]
__device__ float g_vc  [Bn * Hn * NBn * HSn];
__device__ float g_loc [Bn * Tn * Cn];            // local_out -> (in-place) local_norm
__device__ float g_cmp [Bn * Tn * Cn];            // comp_out
__device__ float g_comb[Bn * Tn * Cn];            // gated combination
__device__ float g_gates[Bn * 2];

// ---------------- SGEMM: C[m,n] = sum_k A[m,k] * B[n,k]  (A,B row-major) ----------------
__global__ __launch_bounds__(256, 2)
void sgemm_nt(const float* __restrict__ A, const float* __restrict__ B,
              float* __restrict__ Cmat, int M, int N, int K)
{
    __shared__ float As[8][128];
    __shared__ float Bs[8][128];
    const int tid = threadIdx.x;
    const int tx = tid & 15;        // n microtile
    const int ty = tid >> 4;        // m microtile
    const int lr = tid >> 1;        // load row 0..127
    const int lq = (tid & 1) << 2;  // k quad 0 or 4

    const float* Ab = A + ((size_t)blockIdx.y * 128 + lr) * K + lq;
    const float* Bb = B + ((size_t)blockIdx.x * 128 + lr) * K + lq;

    float acc[8][8];
#pragma unroll
    for (int i = 0; i < 8; ++i)
#pragma unroll
        for (int j = 0; j < 8; ++j) acc[i][j] = 0.f;

    for (int k0 = 0; k0 < K; k0 += 8) {
        float4 av = *(const float4*)(Ab + k0);
        float4 bv = *(const float4*)(Bb + k0);
        __syncthreads();
        As[lq + 0][lr] = av.x; As[lq + 1][lr] = av.y;
        As[lq + 2][lr] = av.z; As[lq + 3][lr] = av.w;
        Bs[lq + 0][lr] = bv.x; Bs[lq + 1][lr] = bv.y;
        Bs[lq + 2][lr] = bv.z; Bs[lq + 3][lr] = bv.w;
        __syncthreads();
#pragma unroll
        for (int kk = 0; kk < 8; ++kk) {
            float a[8], b[8];
            *(float4*)(a)     = *(const float4*)&As[kk][ty * 8];
            *(float4*)(a + 4) = *(const float4*)&As[kk][ty * 8 + 4];
            *(float4*)(b)     = *(const float4*)&Bs[kk][tx * 8];
            *(float4*)(b + 4) = *(const float4*)&Bs[kk][tx * 8 + 4];
#pragma unroll
            for (int i = 0; i < 8; ++i)
#pragma unroll
                for (int j = 0; j < 8; ++j) acc[i][j] = fmaf(a[i], b[j], acc[i][j]);
        }
    }
#pragma unroll
    for (int i = 0; i < 8; ++i) {
        float* Crow = Cmat + ((size_t)blockIdx.y * 128 + ty * 8 + i) * N
                          + (size_t)blockIdx.x * 128 + tx * 8;
        *(float4*)(Crow)     = make_float4(acc[i][0], acc[i][1], acc[i][2], acc[i][3]);
        *(float4*)(Crow + 4) = make_float4(acc[i][4], acc[i][5], acc[i][6], acc[i][7]);
    }
}

// ---------------- Conv1d compression + LN(hs) + exact GELU ----------------
// out[bh, nb, o] = gelu(ln( sum_{i,kk} conv_w[o,i,kk] * In[b, nb*16+kk, h, i] ))
__global__ __launch_bounds__(256)
void conv_compress_kernel(const float* __restrict__ qkv, const float* __restrict__ conv_w,
                          const float* __restrict__ ln_comp_w,
                          float* __restrict__ kc, float* __restrict__ vc)
{
    __shared__ float shW[64 * 33];   // W[o][kk] at fixed i, stride 33 (conflict-free across o)
    __shared__ float shIn[1104];     // In[t] at fixed i, padded every 16 by 1
    __shared__ float sOut[63 * 65];

    const int bh  = blockIdx.x;          // 0..127
    const int sel = blockIdx.y;          // 0 -> k, 1 -> v
    const int b = bh >> 4, h = bh & 15;
    const float* base = qkv + (size_t)b * Tn * 3072 + 1024 + sel * 1024 + h * 64;
    float* out = (sel ? vc : kc) + (size_t)bh * NBn * 64;

    const int tid = threadIdx.x;
    const int og = tid >> 4;   // o = og*4 + s
    const int ng = tid & 15;   // nb = ng*4 + q

    float acc[16];
#pragma unroll
    for (int i = 0; i < 16; ++i) acc[i] = 0.f;

    for (int i = 0; i < 64; ++i) {
        __syncthreads();
        for (int idx = tid; idx < 2048; idx += 256) {
            int o = idx >> 5, kk = idx & 31;
            shW[o * 33 + kk] = conv_w[((size_t)o * 64 + i) * 32 + kk];
        }
        for (int t = tid; t < 1024; t += 256)
            shIn[(t >> 4) * 17 + (t & 15)] = base[(size_t)t * 3072 + i];
        if (tid < 17) shIn[1087 + tid] = 0.f;    // tail safety
        __syncthreads();

#pragma unroll 4
        for (int kk = 0; kk < 32; ++kk) {
            const float w0 = shW[(og * 4 + 0) * 33 + kk];
            const float w1 = shW[(og * 4 + 1) * 33 + kk];
            const float w2 = shW[(og * 4 + 2) * 33 + kk];
            const float w3 = shW[(og * 4 + 3) * 33 + kk];
            const int hi = kk >> 4, lo = kk & 15;
#pragma unroll
            for (int q = 0; q < 4; ++q) {
                int nb = ng * 4 + q;
                float xin = shIn[(nb + hi) * 17 + lo];
                acc[0 + q]  = fmaf(w0, xin, acc[0 + q]);
                acc[4 + q]  = fmaf(w1, xin, acc[4 + q]);
                acc[8 + q]  = fmaf(w2, xin, acc[8 + q]);
                acc[12 + q] = fmaf(w3, xin, acc[12 + q]);
            }
        }
    }
    __syncthreads();
#pragma unroll
    for (int s = 0; s < 4; ++s)
#pragma unroll
        for (int q = 0; q < 4; ++q) {
            int nb = ng * 4 + q;
            if (nb < 63) sOut[nb * 65 + og * 4 + s] = acc[s * 4 + q];
        }
    __syncthreads();

    const int warp = tid >> 5, lane = tid & 31;
    for (int nb = warp; nb < 63; nb += 8) {
        float x0 = sOut[nb * 65 + lane];
        float x1 = sOut[nb * 65 + 32 + lane];
        float sm = x0 + x1, sq = x0 * x0 + x1 * x1;
#pragma unroll
        for (int off = 16; off; off >>= 1) {
            sm += __shfl_xor_sync(0xffffffffu, sm, off);
            sq += __shfl_xor_sync(0xffffffffu, sq, off);
        }
        float mean = sm * (1.f / 64.f);
        float var  = sq * (1.f / 64.f) - mean * mean;
        float inv  = rsqrtf(var + EPSf);
        float z0 = (x0 - mean) * inv * ln_comp_w[lane];
        float z1 = (x1 - mean) * inv * ln_comp_w[32 + lane];
        out[nb * 64 + lane]      = 0.5f * z0 * (1.f + erff(z0 * 0.70710678118654752f));
        out[nb * 64 + 32 + lane] = 0.5f * z1 * (1.f + erff(z1 * 0.70710678118654752f));
    }
}

// ---------------- Local banded causal attention ----------------
// block = (64 queries) x (b,h). Keys j in [i-128, i]. Writes g_loc [B,T,C].
#define LOC_SMEM_FLOATS (64 * 193 + 192 * 64 + 8 * 192)
__global__ __launch_bounds__(256)
void local_attn_kernel(const float* __restrict__ qkv, float* __restrict__ outp)
{
    extern __shared__ float sm[];
    float* Kt    = sm;                  // [d][j], stride 193
    float* V     = sm + 64 * 193;       // [j][d]
    float* probs = V + 192 * 64;        // [warp][192]

    const int qtile = blockIdx.x, bh = blockIdx.y;
    const int b = bh >> 4, h = bh & 15;
    const int qstart = qtile * 64;
    const int kstart = qstart - 128;
    const float* qbase = qkv + (size_t)b * Tn * 3072 + h * 64;

    for (int idx = threadIdx.x; idx < 192 * 64; idx += 256) {
        int j = idx >> 6, d = idx & 63;
        int t = kstart + j;
        float kv = 0.f, vv = 0.f;
        if (t >= 0) {
            const float* p = qbase + (size_t)t * 3072;
            kv = p[1024 + d];
            vv = p[2048 + d];
        }
        Kt[d * 193 + j] = kv;
        V[idx] = vv;
    }
    __syncthreads();

    const int warp = threadIdx.x >> 5, lane = threadIdx.x & 31;
    const int jlo_base = (kstart < 0) ? -kstart : 0;

    for (int r = 0; r < 8; ++r) {
        const int qi = warp * 8 + r;
        const int qg = qstart + qi;
        float qreg[64];
        const float* qp = qbase + (size_t)qg * 3072;
#pragma unroll
        for (int d = 0; d < 64; ++d) qreg[d] = __ldg(qp + d);

        const int jlo = (qi > jlo_base) ? qi : jlo_base;
        const int jhi = qi + 128;

        float mx = -1e30f;
        float sv[6];
#pragma unroll
        for (int m = 0; m < 6; ++m) {
            int j = lane + 32 * m;
            float s = -1e30f;
            if (32 * m <= jhi && 32 * m + 31 >= jlo && j >= jlo && j <= jhi) {
                float a = 0.f;
#pragma unroll
                for (int d = 0; d < 64; ++d) a = fmaf(qreg[d], Kt[d * 193 + j], a);
                s = a * 0.125f;
            }
            sv[m] = s;
            mx = fmaxf(mx, s);
        }
#pragma unroll
        for (int off = 16; off; off >>= 1) mx = fmaxf(mx, __shfl_xor_sync(0xffffffffu, mx, off));

        float sum = 0.f;
#pragma unroll
        for (int m = 0; m < 6; ++m) {
            int j = lane + 32 * m;
            float p = (sv[m] > -1e29f) ? __expf(sv[m] - mx) : 0.f;
            probs[warp * 192 + j] = p;
            sum += p;
        }
#pragma unroll
        for (int off = 16; off; off >>= 1) sum += __shfl_xor_sync(0xffffffffu, sum, off);
        const float invs = 1.f / sum;
        __syncwarp();

        float a0 = 0.f, a1 = 0.f;
        const int d0 = lane * 2;
        const float* pw = probs + warp * 192;
#pragma unroll 4
        for (int j = jlo; j <= jhi; ++j) {
            float p = pw[j];
            float2 v2 = *(const float2*)&V[j * 64 + d0];
            a0 = fmaf(p, v2.x, a0);
            a1 = fmaf(p, v2.y, a1);
        }
        float* op = outp + ((size_t)(b * Tn + qg)) * Cn + h * 64 + d0;
        op[0] = a0 * invs;
        op[1] = a1 * invs;
        __syncwarp();
    }
}

// ---------------- Compressed-KV attention (63 blocks, mask j <= i) ----------------
__global__ __launch_bounds__(256)
void comp_attn_kernel(const float* __restrict__ qkv, const float* __restrict__ kc,
                      const float* __restrict__ vc, float* __restrict__ outp)
{
    __shared__ float Kct[64 * 64];     // [d][j], j<63 (col 63 unused)
    __shared__ float Vc[63 * 64];      // [j][d]
    __shared__ float probs[8 * 64];

    const int bh = blockIdx.y;
    const int b = bh >> 4, h = bh & 15;
    const int qstart = blockIdx.x * 128;

    for (int idx = threadIdx.x; idx < 63 * 64; idx += 256) {
        int j = idx >> 6, d = idx & 63;
        Kct[d * 64 + j] = kc[(size_t)bh * 63 * 64 + idx];
        Vc[idx]         = vc[(size_t)bh * 63 * 64 + idx];
    }
    __syncthreads();

    const int warp = threadIdx.x >> 5, lane = threadIdx.x & 31;
    const float* qbase = qkv + (size_t)b * Tn * 3072 + h * 64;

    for (int r = 0; r < 16; ++r) {
        const int qg = qstart + warp * 16 + r;
        const int nk = (qg < 62 ? qg : 62) + 1;
        float qreg[64];
        const float* qp = qbase + (size_t)qg * 3072;
#pragma unroll
        for (int d = 0; d < 64; ++d) qreg[d] = __ldg(qp + d);

        float mx = -1e30f;
        float sv[2];
#pragma unroll
        for (int m = 0; m < 2; ++m) {
            int j = lane + 32 * m;
            float s = -1e30f;
            if (j < nk) {
                float a = 0.f;
#pragma unroll
                for (int d = 0; d < 64; ++d) a = fmaf(qreg[d], Kct[d * 64 + j], a);
                s = a * 0.125f;
            }
            sv[m] = s;
            mx = fmaxf(mx, s);
        }
#pragma unroll
        for (int off = 16; off; off >>= 1) mx = fmaxf(mx, __shfl_xor_sync(0xffffffffu, mx, off));
        float sum = 0.f;
#pragma unroll
        for (int m = 0; m < 2; ++m) {
            int j = lane + 32 * m;
            float p = (sv[m] > -1e29f) ? __expf(sv[m] - mx) : 0.f;
            probs[warp * 64 + j] = p;
            sum += p;
        }
#pragma unroll
        for (int off = 16; off; off >>= 1) sum += __shfl_xor_sync(0xffffffffu, sum, off);
        const float invs = 1.f / sum;
        __syncwarp();

        float a0 = 0.f, a1 = 0.f;
        const int d0 = lane * 2;
        const float* pw = probs + warp * 64;
        for (int j = 0; j < nk; ++j) {
            float p = pw[j];
            float2 v2 = *(const float2*)&Vc[j * 64 + d0];
            a0 = fmaf(p, v2.x, a0);
            a1 = fmaf(p, v2.y, a1);
        }
        float* op = outp + ((size_t)(b * Tn + qg)) * Cn + h * 64 + d0;
        op[0] = a0 * invs;
        op[1] = a1 * invs;
        __syncwarp();
    }
}

// ---------------- In-place row LayerNorm over C=1024 ----------------
__global__ __launch_bounds__(256)
void ln_rows_kernel(float* __restrict__ buf, const float* __restrict__ w)
{
    __shared__ float rs[8], rq[8], fin[2];
    const size_t row = blockIdx.x;
    float* p = buf + row * 1024;
    float x[4];
    float sm = 0.f, sq = 0.f;
#pragma unroll
    for (int k = 0; k < 4; ++k) {
        x[k] = p[threadIdx.x + k * 256];
        sm += x[k]; sq += x[k] * x[k];
    }
    const int warp = threadIdx.x >> 5, lane = threadIdx.x & 31;
#pragma unroll
    for (int off = 16; off; off >>= 1) {
        sm += __shfl_xor_sync(0xffffffffu, sm, off);
        sq += __shfl_xor_sync(0xffffffffu, sq, off);
    }
    if (lane == 0) { rs[warp] = sm; rq[warp] = sq; }
    __syncthreads();
    if (threadIdx.x == 0) {
        float a = 0.f, c = 0.f;
#pragma unroll
        for (int i = 0; i < 8; ++i) { a += rs[i]; c += rq[i]; }
        float mean = a * (1.f / 1024.f);
        float var  = c * (1.f / 1024.f) - mean * mean;
        fin[0] = mean;
        fin[1] = rsqrtf(var + EPSf);
    }
    __syncthreads();
    const float mean = fin[0], inv = fin[1];
#pragma unroll
    for (int k = 0; k < 4; ++k) {
        int c = threadIdx.x + k * 256;
        p[c] = (x[k] - mean) * inv * w[c];
    }
}

// ---------------- Gating MLP (one block per batch) ----------------
__global__ __launch_bounds__(256)
void gate_kernel(const float* __restrict__ localn, const float* __restrict__ comp,
                 const float* __restrict__ w1, const float* __restrict__ lnw,
                 const float* __restrict__ w2, float* __restrict__ gates)
{
    __shared__ float feats[2048];
    __shared__ float hsh[1024];
    __shared__ float rs[8], rq[8], fin[2];
    __shared__ float rl0[8], rl1[8];

    const int b = blockIdx.x;
    for (int idx = threadIdx.x; idx < 1024; idx += 256) {
        feats[idx]        = localn[((size_t)b * Tn + 1023) * Cn + idx];
        feats[1024 + idx] = comp  [((size_t)b * Tn + 1023) * Cn + idx];
    }
    __syncthreads();

#pragma unroll
    for (int jj = 0; jj < 4; ++jj) {
        int j = jj * 256 + threadIdx.x;
        const float4* wr = (const float4*)(w1 + (size_t)j * 2048);
        float a = 0.f;
        for (int c4 = 0; c4 < 512; ++c4) {
            float4 wv = __ldg(wr + c4);
            float4 fv = *(const float4*)&feats[c4 * 4];
            a += wv.x * fv.x + wv.y * fv.y + wv.z * fv.z + wv.w * fv.w;
        }
        hsh[j] = a;
    }
    __syncthreads();

    float sm = 0.f, sq = 0.f;
#pragma unroll
    for (int jj = 0; jj < 4; ++jj) {
        float v = hsh[jj * 256 + threadIdx.x];
        sm += v; sq += v * v;
    }
    const int warp = threadIdx.x >> 5, lane = threadIdx.x & 31;
#pragma unroll
    for (int off = 16; off; off >>= 1) {
        sm += __shfl_xor_sync(0xffffffffu, sm, off);
        sq += __shfl_xor_sync(0xffffffffu, sq, off);
    }
    if (lane == 0) { rs[warp] = sm; rq[warp] = sq; }
    __syncthreads();
    if (threadIdx.x == 0) {
        float a = 0.f, c = 0.f;
#pragma unroll
        for (int i = 0; i < 8; ++i) { a += rs[i]; c += rq[i]; }
        float mean = a * (1.f / 1024.f);
        float var  = c * (1.f / 1024.f) - mean * mean;
        fin[0] = mean;
        fin[1] = rsqrtf(var + EPSf);
    }
    __syncthreads();
    const float mean = fin[0], inv = fin[1];

    float l0 = 0.f, l1 = 0.f;
#pragma unroll
    for (int jj = 0; jj < 4; ++jj) {
        int j = jj * 256 + threadIdx.x;
        float hp = (hsh[j] - mean) * inv * lnw[j];
        hp = fmaxf(hp, 0.f);
        l0 = fmaf(hp, w2[j], l0);
        l1 = fmaf(hp, w2[1024 + j], l1);
    }
#pragma unroll
    for (int off = 16; off; off >>= 1) {
        l0 += __shfl_xor_sync(0xffffffffu, l0, off);
        l1 += __shfl_xor_sync(0xffffffffu, l1, off);
    }
    if (lane == 0) { rl0[warp] = l0; rl1[warp] = l1; }
    __syncthreads();
    if (threadIdx.x == 0) {
        float a = 0.f, c = 0.f;
#pragma unroll
        for (int i = 0; i < 8; ++i) { a += rl0[i]; c += rl1[i]; }
        float m = fmaxf(a, c);
        float e0 = __expf(a - m), e1 = __expf(c - m);
        float s = e0 + e1;
        gates[2 * b]     = e0 / s;
        gates[2 * b + 1] = e1 / s;
    }
}

// ---------------- Gated combination ----------------
__global__ __launch_bounds__(256)
void combine_kernel(const float* __restrict__ ln, const float* __restrict__ cp,
                    const float* __restrict__ gates, float* __restrict__ out)
{
    const int idx = blockIdx.x * 256 + threadIdx.x;   // float4 index (2M total)
    const int b = idx >> 18;                          // 2^18 float4 per batch
    const float g0 = gates[2 * b], g1 = gates[2 * b + 1];
    float4 a = ((const float4*)ln)[idx];
    float4 c = ((const float4*)cp)[idx];
    ((float4*)out)[idx] = make_float4(g0 * a.x + g1 * c.x, g0 * a.y + g1 * c.y,
                                      g0 * a.z + g1 * c.z, g0 * a.w + g1 * c.w);
}

// ---------------- launch ----------------
extern "C" void kernel_launch(void* const* d_in, const int* in_sizes, int n_in,
                              void* d_out, int out_size)
{
    const float* x          = (const float*)d_in[0];
    const float* c_attn_w   = (const float*)d_in[1];
    const float* conv_w     = (const float*)d_in[2];
    const float* ln_comp_w  = (const float*)d_in[3];
    const float* ln_local_w = (const float*)d_in[4];
    const float* gate_w1    = (const float*)d_in[5];
    const float* gate_ln_w  = (const float*)d_in[6];
    const float* gate_w2    = (const float*)d_in[7];
    const float* c_proj_w   = (const float*)d_in[8];
    float* y = (float*)d_out;

    float *qkv, *kc, *vc, *loc, *cmp, *comb, *gates;
    cudaGetSymbolAddress((void**)&qkv,   g_qkv);
    cudaGetSymbolAddress((void**)&kc,    g_kc);
    cudaGetSymbolAddress((void**)&vc,    g_vc);
    cudaGetSymbolAddress((void**)&loc,   g_loc);
    cudaGetSymbolAddress((void**)&cmp,   g_cmp);
    cudaGetSymbolAddress((void**)&comb,  g_comb);
    cudaGetSymbolAddress((void**)&gates, g_gates);

    cudaFuncSetAttribute(local_attn_kernel, cudaFuncAttributeMaxDynamicSharedMemorySize,
                         LOC_SMEM_FLOATS * (int)sizeof(float));

    // 1) QKV projection: [8192,1024] x [3072,1024]^T
    sgemm_nt<<<dim3(3072 / 128, 8192 / 128), 256>>>(x, c_attn_w, qkv, 8192, 3072, 1024);
    // 2) compression conv + LN + GELU for k and v
    conv_compress_kernel<<<dim3(Bn * Hn, 2), 256>>>(qkv, conv_w, ln_comp_w, kc, vc);
    // 3) local banded attention -> g_loc
    local_attn_kernel<<<dim3(Tn / 64, Bn * Hn), 256, LOC_SMEM_FLOATS * sizeof(float)>>>(qkv, loc);
    // 4) in-place LN over C on local output
    ln_rows_kernel<<<Bn * Tn, 256>>>(loc, ln_local_w);
    // 5) compressed attention -> g_cmp
    comp_attn_kernel<<<dim3(Tn / 128, Bn * Hn), 256>>>(qkv, kc, vc, cmp);
    // 6) gating from last-token features
    gate_kernel<<<Bn, 256>>>(loc, cmp, gate_w1, gate_ln_w, gate_w2, gates);
    // 7) gated combine
    combine_kernel<<<(Bn * Tn * Cn / 4) / 256, 256>>>(loc, cmp, gates, comb);
    // 8) output projection
    sgemm_nt<<<dim3(1024 / 128, 8192 / 128), 256>>>(comb, c_proj_w, y, 8192, 1024, 1024);
}

// round 10
// speedup vs baseline: 1.0002x; 1.0002x over previous
#include <cuda_runtime.h>
#include <cuda_bf16.h>
#include <math.h>

// Problem constants
#define Bn   8
#define Tn   1024
#define Cn   1024
#define Hn   16
#define HSn  64
#define NBn  63
#define WINn 128
#define EPSf 1e-5f

// ---------------- scratch (device globals; no allocation) ----------------
__device__ float g_qkv [Bn * Tn * 3 * Cn];        // [B,T,3C]
__device__ float g_kc  [Bn * Hn * NBn * HSn];     // [B,H,NB,hs]
__device__ float g_vc  [Bn * Hn * NBn * HSn];
__device__ float g_loc [Bn * Tn * Cn];            // local_out -> (in-place) local_norm
__device__ float g_cmp [Bn * Tn * Cn];            // comp_out
__device__ float g_comb[Bn * Tn * Cn];            // gated combination
__device__ float g_gates[Bn * 2];

// ---------------- SGEMM: C[m,n] = sum_k A[m,k] * B[n,k]  (A,B row-major) ----------------
__global__ __launch_bounds__(256, 2)
void sgemm_nt(const float* __restrict__ A, const float* __restrict__ B,
              float* __restrict__ Cmat, int M, int N, int K)
{
    __shared__ float As[8][128];
    __shared__ float Bs[8][128];
    const int tid = threadIdx.x;
    const int tx = tid & 15;        // n microtile
    const int ty = tid >> 4;        // m microtile
    const int lr = tid >> 1;        // load row 0..127
    const int lq = (tid & 1) << 2;  // k quad 0 or 4

    const float* Ab = A + ((size_t)blockIdx.y * 128 + lr) * K + lq;
    const float* Bb = B + ((size_t)blockIdx.x * 128 + lr) * K + lq;

    float acc[8][8];
#pragma unroll
    for (int i = 0; i < 8; ++i)
#pragma unroll
        for (int j = 0; j < 8; ++j) acc[i][j] = 0.f;

    for (int k0 = 0; k0 < K; k0 += 8) {
        float4 av = *(const float4*)(Ab + k0);
        float4 bv = *(const float4*)(Bb + k0);
        __syncthreads();
        As[lq + 0][lr] = av.x; As[lq + 1][lr] = av.y;
        As[lq + 2][lr] = av.z; As[lq + 3][lr] = av.w;
        Bs[lq + 0][lr] = bv.x; Bs[lq + 1][lr] = bv.y;
        Bs[lq + 2][lr] = bv.z; Bs[lq + 3][lr] = bv.w;
        __syncthreads();
#pragma unroll
        for (int kk = 0; kk < 8; ++kk) {
            float a[8], b[8];
            *(float4*)(a)     = *(const float4*)&As[kk][ty * 8];
            *(float4*)(a + 4) = *(const float4*)&As[kk][ty * 8 + 4];
            *(float4*)(b)     = *(const float4*)&Bs[kk][tx * 8];
            *(float4*)(b + 4) = *(const float4*)&Bs[kk][tx * 8 + 4];
#pragma unroll
            for (int i = 0; i < 8; ++i)
#pragma unroll
                for (int j = 0; j < 8; ++j) acc[i][j] = fmaf(a[i], b[j], acc[i][j]);
        }
    }
#pragma unroll
    for (int i = 0; i < 8; ++i) {
        float* Crow = Cmat + ((size_t)blockIdx.y * 128 + ty * 8 + i) * N
                          + (size_t)blockIdx.x * 128 + tx * 8;
        *(float4*)(Crow)     = make_float4(acc[i][0], acc[i][1], acc[i][2], acc[i][3]);
        *(float4*)(Crow + 4) = make_float4(acc[i][4], acc[i][5], acc[i][6], acc[i][7]);
    }
}

// ---------------- Conv1d compression + LN(hs) + exact GELU ----------------
// out[bh, nb, o] = gelu(ln( sum_{i,kk} conv_w[o,i,kk] * In[b, nb*16+kk, h, i] ))
__global__ __launch_bounds__(256)
void conv_compress_kernel(const float* __restrict__ qkv, const float* __restrict__ conv_w,
                          const float* __restrict__ ln_comp_w,
                          float* __restrict__ kc, float* __restrict__ vc)
{
    __shared__ float shW[64 * 33];   // W[o][kk] at fixed i, stride 33 (conflict-free across o)
    __shared__ float shIn[1104];     // In[t] at fixed i, padded every 16 by 1
    __shared__ float sOut[63 * 65];

    const int bh  = blockIdx.x;          // 0..127
    const int sel = blockIdx.y;          // 0 -> k, 1 -> v
    const int b = bh >> 4, h = bh & 15;
    const float* base = qkv + (size_t)b * Tn * 3072 + 1024 + sel * 1024 + h * 64;
    float* out = (sel ? vc : kc) + (size_t)bh * NBn * 64;

    const int tid = threadIdx.x;
    const int og = tid >> 4;   // o = og*4 + s
    const int ng = tid & 15;   // nb = ng*4 + q

    float acc[16];
#pragma unroll
    for (int i = 0; i < 16; ++i) acc[i] = 0.f;

    for (int i = 0; i < 64; ++i) {
        __syncthreads();
        for (int idx = tid; idx < 2048; idx += 256) {
            int o = idx >> 5, kk = idx & 31;
            shW[o * 33 + kk] = conv_w[((size_t)o * 64 + i) * 32 + kk];
        }
        for (int t = tid; t < 1024; t += 256)
            shIn[(t >> 4) * 17 + (t & 15)] = base[(size_t)t * 3072 + i];
        if (tid < 17) shIn[1087 + tid] = 0.f;    // tail safety
        __syncthreads();

#pragma unroll 4
        for (int kk = 0; kk < 32; ++kk) {
            const float w0 = shW[(og * 4 + 0) * 33 + kk];
            const float w1 = shW[(og * 4 + 1) * 33 + kk];
            const float w2 = shW[(og * 4 + 2) * 33 + kk];
            const float w3 = shW[(og * 4 + 3) * 33 + kk];
            const int hi = kk >> 4, lo = kk & 15;
#pragma unroll
            for (int q = 0; q < 4; ++q) {
                int nb = ng * 4 + q;
                float xin = shIn[(nb + hi) * 17 + lo];
                acc[0 + q]  = fmaf(w0, xin, acc[0 + q]);
                acc[4 + q]  = fmaf(w1, xin, acc[4 + q]);
                acc[8 + q]  = fmaf(w2, xin, acc[8 + q]);
                acc[12 + q] = fmaf(w3, xin, acc[12 + q]);
            }
        }
    }
    __syncthreads();
#pragma unroll
    for (int s = 0; s < 4; ++s)
#pragma unroll
        for (int q = 0; q < 4; ++q) {
            int nb = ng * 4 + q;
            if (nb < 63) sOut[nb * 65 + og * 4 + s] = acc[s * 4 + q];
        }
    __syncthreads();

    const int warp = tid >> 5, lane = tid & 31;
    for (int nb = warp; nb < 63; nb += 8) {
        float x0 = sOut[nb * 65 + lane];
        float x1 = sOut[nb * 65 + 32 + lane];
        float sm = x0 + x1, sq = x0 * x0 + x1 * x1;
#pragma unroll
        for (int off = 16; off; off >>= 1) {
            sm += __shfl_xor_sync(0xffffffffu, sm, off);
            sq += __shfl_xor_sync(0xffffffffu, sq, off);
        }
        float mean = sm * (1.f / 64.f);
        float var  = sq * (1.f / 64.f) - mean * mean;
        float inv  = rsqrtf(var + EPSf);
        float z0 = (x0 - mean) * inv * ln_comp_w[lane];
        float z1 = (x1 - mean) * inv * ln_comp_w[32 + lane];
        out[nb * 64 + lane]      = 0.5f * z0 * (1.f + erff(z0 * 0.70710678118654752f));
        out[nb * 64 + 32 + lane] = 0.5f * z1 * (1.f + erff(z1 * 0.70710678118654752f));
    }
}

// ---------------- Local banded causal attention ----------------
// block = (64 queries) x (b,h). Keys j in [i-128, i]. Writes g_loc [B,T,C].
#define LOC_SMEM_FLOATS (64 * 193 + 192 * 64 + 8 * 192)
__global__ __launch_bounds__(256)
void local_attn_kernel(const float* __restrict__ qkv, float* __restrict__ outp)
{
    extern __shared__ float sm[];
    float* Kt    = sm;                  // [d][j], stride 193
    float* V     = sm + 64 * 193;       // [j][d]
    float* probs = V + 192 * 64;        // [warp][192]

    const int qtile = blockIdx.x, bh = blockIdx.y;
    const int b = bh >> 4, h = bh & 15;
    const int qstart = qtile * 64;
    const int kstart = qstart - 128;
    const float* qbase = qkv + (size_t)b * Tn * 3072 + h * 64;

    for (int idx = threadIdx.x; idx < 192 * 64; idx += 256) {
        int j = idx >> 6, d = idx & 63;
        int t = kstart + j;
        float kv = 0.f, vv = 0.f;
        if (t >= 0) {
            const float* p = qbase + (size_t)t * 3072;
            kv = p[1024 + d];
            vv = p[2048 + d];
        }
        Kt[d * 193 + j] = kv;
        V[idx] = vv;
    }
    __syncthreads();

    const int warp = threadIdx.x >> 5, lane = threadIdx.x & 31;
    const int jlo_base = (kstart < 0) ? -kstart : 0;

    for (int r = 0; r < 8; ++r) {
        const int qi = warp * 8 + r;
        const int qg = qstart + qi;
        float qreg[64];
        const float* qp = qbase + (size_t)qg * 3072;
#pragma unroll
        for (int d = 0; d < 64; ++d) qreg[d] = __ldg(qp + d);

        const int jlo = (qi > jlo_base) ? qi : jlo_base;
        const int jhi = qi + 128;

        float mx = -1e30f;
        float sv[6];
#pragma unroll
        for (int m = 0; m < 6; ++m) {
            int j = lane + 32 * m;
            float s = -1e30f;
            if (32 * m <= jhi && 32 * m + 31 >= jlo && j >= jlo && j <= jhi) {
                float a = 0.f;
#pragma unroll
                for (int d = 0; d < 64; ++d) a = fmaf(qreg[d], Kt[d * 193 + j], a);
                s = a * 0.125f;
            }
            sv[m] = s;
            mx = fmaxf(mx, s);
        }
#pragma unroll
        for (int off = 16; off; off >>= 1) mx = fmaxf(mx, __shfl_xor_sync(0xffffffffu, mx, off));

        float sum = 0.f;
#pragma unroll
        for (int m = 0; m < 6; ++m) {
            int j = lane + 32 * m;
            float p = (sv[m] > -1e29f) ? __expf(sv[m] - mx) : 0.f;
            probs[warp * 192 + j] = p;
            sum += p;
        }
#pragma unroll
        for (int off = 16; off; off >>= 1) sum += __shfl_xor_sync(0xffffffffu, sum, off);
        const float invs = 1.f / sum;
        __syncwarp();

        float a0 = 0.f, a1 = 0.f;
        const int d0 = lane * 2;
        const float* pw = probs + warp * 192;
#pragma unroll 4
        for (int j = jlo; j <= jhi; ++j) {
            float p = pw[j];
            float2 v2 = *(const float2*)&V[j * 64 + d0];
            a0 = fmaf(p, v2.x, a0);
            a1 = fmaf(p, v2.y, a1);
        }
        float* op = outp + ((size_t)(b * Tn + qg)) * Cn + h * 64 + d0;
        op[0] = a0 * invs;
        op[1] = a1 * invs;
        __syncwarp();
    }
}

// ---------------- Compressed-KV attention (63 blocks, mask j <= i) ----------------
__global__ __launch_bounds__(256)
void comp_attn_kernel(const float* __restrict__ qkv, const float* __restrict__ kc,
                      const float* __restrict__ vc, float* __restrict__ outp)
{
    __shared__ float Kct[64 * 64];     // [d][j], j<63 (col 63 unused)
    __shared__ float Vc[63 * 64];      // [j][d]
    __shared__ float probs[8 * 64];

    const int bh = blockIdx.y;
    const int b = bh >> 4, h = bh & 15;
    const int qstart = blockIdx.x * 128;

    for (int idx = threadIdx.x; idx < 63 * 64; idx += 256) {
        int j = idx >> 6, d = idx & 63;
        Kct[d * 64 + j] = kc[(size_t)bh * 63 * 64 + idx];
        Vc[idx]         = vc[(size_t)bh * 63 * 64 + idx];
    }
    __syncthreads();

    const int warp = threadIdx.x >> 5, lane = threadIdx.x & 31;
    const float* qbase = qkv + (size_t)b * Tn * 3072 + h * 64;

    for (int r = 0; r < 16; ++r) {
        const int qg = qstart + warp * 16 + r;
        const int nk = (qg < 62 ? qg : 62) + 1;
        float qreg[64];
        const float* qp = qbase + (size_t)qg * 3072;
#pragma unroll
        for (int d = 0; d < 64; ++d) qreg[d] = __ldg(qp + d);

        float mx = -1e30f;
        float sv[2];
#pragma unroll
        for (int m = 0; m < 2; ++m) {
            int j = lane + 32 * m;
            float s = -1e30f;
            if (j < nk) {
                float a = 0.f;
#pragma unroll
                for (int d = 0; d < 64; ++d) a = fmaf(qreg[d], Kct[d * 64 + j], a);
                s = a * 0.125f;
            }
            sv[m] = s;
            mx = fmaxf(mx, s);
        }
#pragma unroll
        for (int off = 16; off; off >>= 1) mx = fmaxf(mx, __shfl_xor_sync(0xffffffffu, mx, off));
        float sum = 0.f;
#pragma unroll
        for (int m = 0; m < 2; ++m) {
            int j = lane + 32 * m;
            float p = (sv[m] > -1e29f) ? __expf(sv[m] - mx) : 0.f;
            probs[warp * 64 + j] = p;
            sum += p;
        }
#pragma unroll
        for (int off = 16; off; off >>= 1) sum += __shfl_xor_sync(0xffffffffu, sum, off);
        const float invs = 1.f / sum;
        __syncwarp();

        float a0 = 0.f, a1 = 0.f;
        const int d0 = lane * 2;
        const float* pw = probs + warp * 64;
        for (int j = 0; j < nk; ++j) {
            float p = pw[j];
            float2 v2 = *(const float2*)&Vc[j * 64 + d0];
            a0 = fmaf(p, v2.x, a0);
            a1 = fmaf(p, v2.y, a1);
        }
        float* op = outp + ((size_t)(b * Tn + qg)) * Cn + h * 64 + d0;
        op[0] = a0 * invs;
        op[1] = a1 * invs;
        __syncwarp();
    }
}

// ---------------- In-place row LayerNorm over C=1024 ----------------
__global__ __launch_bounds__(256)
void ln_rows_kernel(float* __restrict__ buf, const float* __restrict__ w)
{
    __shared__ float rs[8], rq[8], fin[2];
    const size_t row = blockIdx.x;
    float* p = buf + row * 1024;
    float x[4];
    float sm = 0.f, sq = 0.f;
#pragma unroll
    for (int k = 0; k < 4; ++k) {
        x[k] = p[threadIdx.x + k * 256];
        sm += x[k]; sq += x[k] * x[k];
    }
    const int warp = threadIdx.x >> 5, lane = threadIdx.x & 31;
#pragma unroll
    for (int off = 16; off; off >>= 1) {
        sm += __shfl_xor_sync(0xffffffffu, sm, off);
        sq += __shfl_xor_sync(0xffffffffu, sq, off);
    }
    if (lane == 0) { rs[warp] = sm; rq[warp] = sq; }
    __syncthreads();
    if (threadIdx.x == 0) {
        float a = 0.f, c = 0.f;
#pragma unroll
        for (int i = 0; i < 8; ++i) { a += rs[i]; c += rq[i]; }
        float mean = a * (1.f / 1024.f);
        float var  = c * (1.f / 1024.f) - mean * mean;
        fin[0] = mean;
        fin[1] = rsqrtf(var + EPSf);
    }
    __syncthreads();
    const float mean = fin[0], inv = fin[1];
#pragma unroll
    for (int k = 0; k < 4; ++k) {
        int c = threadIdx.x + k * 256;
        p[c] = (x[k] - mean) * inv * w[c];
    }
}

// ---------------- Gating MLP (one block per batch) ----------------
__global__ __launch_bounds__(256)
void gate_kernel(const float* __restrict__ localn, const float* __restrict__ comp,
                 const float* __restrict__ w1, const float* __restrict__ lnw,
                 const float* __restrict__ w2, float* __restrict__ gates)
{
    __shared__ float feats[2048];
    __shared__ float hsh[1024];
    __shared__ float rs[8], rq[8], fin[2];
    __shared__ float rl0[8], rl1[8];

    const int b = blockIdx.x;
    for (int idx = threadIdx.x; idx < 1024; idx += 256) {
        feats[idx]        = localn[((size_t)b * Tn + 1023) * Cn + idx];
        feats[1024 + idx] = comp  [((size_t)b * Tn + 1023) * Cn + idx];
    }
    __syncthreads();

#pragma unroll
    for (int jj = 0; jj < 4; ++jj) {
        int j = jj * 256 + threadIdx.x;
        const float4* wr = (const float4*)(w1 + (size_t)j * 2048);
        float a = 0.f;
        for (int c4 = 0; c4 < 512; ++c4) {
            float4 wv = __ldg(wr + c4);
            float4 fv = *(const float4*)&feats[c4 * 4];
            a += wv.x * fv.x + wv.y * fv.y + wv.z * fv.z + wv.w * fv.w;
        }
        hsh[j] = a;
    }
    __syncthreads();

    float sm = 0.f, sq = 0.f;
#pragma unroll
    for (int jj = 0; jj < 4; ++jj) {
        float v = hsh[jj * 256 + threadIdx.x];
        sm += v; sq += v * v;
    }
    const int warp = threadIdx.x >> 5, lane = threadIdx.x & 31;
#pragma unroll
    for (int off = 16; off; off >>= 1) {
        sm += __shfl_xor_sync(0xffffffffu, sm, off);
        sq += __shfl_xor_sync(0xffffffffu, sq, off);
    }
    if (lane == 0) { rs[warp] = sm; rq[warp] = sq; }
    __syncthreads();
    if (threadIdx.x == 0) {
        float a = 0.f, c = 0.f;
#pragma unroll
        for (int i = 0; i < 8; ++i) { a += rs[i]; c += rq[i]; }
        float mean = a * (1.f / 1024.f);
        float var  = c * (1.f / 1024.f) - mean * mean;
        fin[0] = mean;
        fin[1] = rsqrtf(var + EPSf);
    }
    __syncthreads();
    const float mean = fin[0], inv = fin[1];

    float l0 = 0.f, l1 = 0.f;
#pragma unroll
    for (int jj = 0; jj < 4; ++jj) {
        int j = jj * 256 + threadIdx.x;
        float hp = (hsh[j] - mean) * inv * lnw[j];
        hp = fmaxf(hp, 0.f);
        l0 = fmaf(hp, w2[j], l0);
        l1 = fmaf(hp, w2[1024 + j], l1);
    }
#pragma unroll
    for (int off = 16; off; off >>= 1) {
        l0 += __shfl_xor_sync(0xffffffffu, l0, off);
        l1 += __shfl_xor_sync(0xffffffffu, l1, off);
    }
    if (lane == 0) { rl0[warp] = l0; rl1[warp] = l1; }
    __syncthreads();
    if (threadIdx.x == 0) {
        float a = 0.f, c = 0.f;
#pragma unroll
        for (int i = 0; i < 8; ++i) { a += rl0[i]; c += rl1[i]; }
        float m = fmaxf(a, c);
        float e0 = __expf(a - m), e1 = __expf(c - m);
        float s = e0 + e1;
        gates[2 * b]     = e0 / s;
        gates[2 * b + 1] = e1 / s;
    }
}

// ---------------- Gated combination ----------------
__global__ __launch_bounds__(256)
void combine_kernel(const float* __restrict__ ln, const float* __restrict__ cp,
                    const float* __restrict__ gates, float* __restrict__ out)
{
    const int idx = blockIdx.x * 256 + threadIdx.x;   // float4 index (2M total)
    const int b = idx >> 18;                          // 2^18 float4 per batch
    const float g0 = gates[2 * b], g1 = gates[2 * b + 1];
    float4 a = ((const float4*)ln)[idx];
    float4 c = ((const float4*)cp)[idx];
    ((float4*)out)[idx] = make_float4(g0 * a.x + g1 * c.x, g0 * a.y + g1 * c.y,
                                      g0 * a.z + g1 * c.z, g0 * a.w + g1 * c.w);
}

// ---------------- launch ----------------
extern "C" void kernel_launch(void* const* d_in, const int* in_sizes, int n_in,
                              void* d_out, int out_size)
{
    const float* x          = (const float*)d_in[0];
    const float* c_attn_w   = (const float*)d_in[1];
    const float* conv_w     = (const float*)d_in[2];
    const float* ln_comp_w  = (const float*)d_in[3];
    const float* ln_local_w = (const float*)d_in[4];
    const float* gate_w1    = (const float*)d_in[5];
    const float* gate_ln_w  = (const float*)d_in[6];
    const float* gate_w2    = (const float*)d_in[7];
    const float* c_proj_w   = (const float*)d_in[8];
    float* y = (float*)d_out;

    float *qkv, *kc, *vc, *loc, *cmp, *comb, *gates;
    cudaGetSymbolAddress((void**)&qkv,   g_qkv);
    cudaGetSymbolAddress((void**)&kc,    g_kc);
    cudaGetSymbolAddress((void**)&vc,    g_vc);
    cudaGetSymbolAddress((void**)&loc,   g_loc);
    cudaGetSymbolAddress((void**)&cmp,   g_cmp);
    cudaGetSymbolAddress((void**)&comb,  g_comb);
    cudaGetSymbolAddress((void**)&gates, g_gates);

    cudaFuncSetAttribute(local_attn_kernel, cudaFuncAttributeMaxDynamicSharedMemorySize,
                         LOC_SMEM_FLOATS * (int)sizeof(float));

    // 1) QKV projection: [8192,1024] x [3072,1024]^T
    sgemm_nt<<<dim3(3072 / 128, 8192 / 128), 256>>>(x, c_attn_w, qkv, 8192, 3072, 1024);
    // 2) compression conv + LN + GELU for k and v
    conv_compress_kernel<<<dim3(Bn * Hn, 2), 256>>>(qkv, conv_w, ln_comp_w, kc, vc);
    // 3) local banded attention -> g_loc
    local_attn_kernel<<<dim3(Tn / 64, Bn * Hn), 256, LOC_SMEM_FLOATS * sizeof(float)>>>(qkv, loc);
    // 4) in-place LN over C on local output
    ln_rows_kernel<<<Bn * Tn, 256>>>(loc, ln_local_w);
    // 5) compressed attention -> g_cmp
    comp_attn_kernel<<<dim3(Tn / 128, Bn * Hn), 256>>>(qkv, kc, vc, cmp);
    // 6) gating from last-token features
    gate_kernel<<<Bn, 256>>>(loc, cmp, gate_w1, gate_ln_w, gate_w2, gates);
    // 7) gated combine
    combine_kernel<<<(Bn * Tn * Cn / 4) / 256, 256>>>(loc, cmp, gates, comb);
    // 8) output projection
    sgemm_nt<<<dim3(1024 / 128, 8192 / 128), 256>>>(comb, c_proj_w, y, 8192, 1024, 1024);
}